// round 3
// baseline (speedup 1.0000x reference)
#include <cuda_runtime.h>
#include <cuda_bf16.h>

// DistMult edge scoring:
//   out[r, e] = sigmoid( sum_d h[src[r,e], d] * W[r, d] * h[dst[r,e], d] )
// Shapes: h [100000, 128] f32, W [6, 128] f32, src/dst [6, 200000] INT32
// (JAX default x64-disabled downcasts the reference's int64 to int32),
// out [6, 200000] f32.
//
// One warp per edge. Row = 128 f32 = 512 B = 32 lanes x float4, fully
// coalesced. h (51.2 MB) fits in ~126 MB L2 -> warmed replays are
// L2-resident. Memory-bound; floor ~110 us at the LTS cap.

#define N_HID 128
#define E_PER_REL 200000
#define N_REL 6
#define TOTAL_EDGES (N_REL * E_PER_REL)

__global__ __launch_bounds__(256, 8)
void distmult_kernel(const float* __restrict__ h,
                     const float* __restrict__ W,
                     const int* __restrict__ src_idx,
                     const int* __restrict__ dst_idx,
                     float* __restrict__ out) {
    const int warp_global = (blockIdx.x * blockDim.x + threadIdx.x) >> 5;
    const int lane = threadIdx.x & 31;
    if (warp_global >= TOTAL_EDGES) return;

    const int rel = warp_global / E_PER_REL;

    // Warp-uniform index loads (broadcast within warp).
    const int s = __ldg(src_idx + warp_global);
    const int d = __ldg(dst_idx + warp_global);

    const float4* __restrict__ hs =
        reinterpret_cast<const float4*>(h + (long long)s * N_HID);
    const float4* __restrict__ hd =
        reinterpret_cast<const float4*>(h + (long long)d * N_HID);
    const float4* __restrict__ wr =
        reinterpret_cast<const float4*>(W + rel * N_HID);

    // Three independent 16B loads per lane -> MLP=3 per warp.
    const float4 a = __ldg(hs + lane);
    const float4 b = __ldg(hd + lane);
    const float4 w = __ldg(wr + lane);

    float acc = a.x * w.x * b.x;
    acc = fmaf(a.y * w.y, b.y, acc);
    acc = fmaf(a.z * w.z, b.z, acc);
    acc = fmaf(a.w * w.w, b.w, acc);

    // Butterfly reduction across the warp.
    #pragma unroll
    for (int off = 16; off > 0; off >>= 1)
        acc += __shfl_xor_sync(0xFFFFFFFFu, acc, off);

    if (lane == 0)
        out[warp_global] = 1.0f / (1.0f + __expf(-acc));
}

extern "C" void kernel_launch(void* const* d_in, const int* in_sizes, int n_in,
                              void* d_out, int out_size) {
    const float* h   = (const float*)d_in[0];
    const float* W   = (const float*)d_in[1];
    const int*   src = (const int*)d_in[2];
    const int*   dst = (const int*)d_in[3];
    float* out = (float*)d_out;

    const int threads = 256;                 // 8 warps / block
    const int warps_per_block = threads / 32;
    const int blocks = (TOTAL_EDGES + warps_per_block - 1) / warps_per_block;

    distmult_kernel<<<blocks, threads>>>(h, W, src, dst, out);
}

// round 4
// speedup vs baseline: 1.9070x; 1.9070x over previous
#include <cuda_runtime.h>
#include <cuda_bf16.h>

// DistMult edge scoring:
//   out[r, e] = sigmoid( sum_d h[src[r,e], d] * W[r, d] * h[dst[r,e], d] )
// h [100000,128] f32, W [6,128] f32, src/dst [6,200000] int32, out [6,200000] f32.
//
// R4: 8 lanes per edge (4 edges/warp), W hoisted to registers via a
// per-relation grid (blockIdx.y = rel) with a grid-stride loop.
// 200000 edges/rel = 1250 blocks x 32 edges x 5 iters exactly.
// Bottleneck per R3 ncu is L1tex + issue, not DRAM/L2: this cuts L1 data
// traffic by 1/3 (no per-edge W stream) and issue slots per edge by ~2x.

#define N_HID 128
#define E_PER_REL 200000
#define N_REL 6
#define BLOCK 256
#define EDGES_PER_BLOCK 32   // 256 threads / 8 lanes per edge
#define GRID_X 1250          // 1250 * 32 * 5 == 200000, no tail

__global__ __launch_bounds__(BLOCK, 4)
void distmult_kernel(const float4* __restrict__ h4,
                     const float4* __restrict__ W4,
                     const int* __restrict__ src_idx,
                     const int* __restrict__ dst_idx,
                     float* __restrict__ out) {
    const int rel   = blockIdx.y;
    const int sub   = threadIdx.x & 7;    // lane within 8-lane edge group
    const int group = threadIdx.x >> 3;   // edge slot within block: 0..31

    // Preload this relation's W row: lane sub owns float4 chunks {sub, sub+8, sub+16, sub+24}.
    const float4* __restrict__ wr = W4 + rel * (N_HID / 4);
    const float4 w0 = __ldg(wr + sub);
    const float4 w1 = __ldg(wr + sub + 8);
    const float4 w2 = __ldg(wr + sub + 16);
    const float4 w3 = __ldg(wr + sub + 24);

    const int* __restrict__ srcR = src_idx + rel * E_PER_REL;
    const int* __restrict__ dstR = dst_idx + rel * E_PER_REL;
    float* __restrict__ outR = out + rel * E_PER_REL;

    for (int e = blockIdx.x * EDGES_PER_BLOCK + group; e < E_PER_REL;
         e += GRID_X * EDGES_PER_BLOCK) {
        const int s = __ldg(srcR + e);   // broadcast across the 8-lane group
        const int d = __ldg(dstR + e);

        const float4* __restrict__ hs = h4 + (long long)s * (N_HID / 4);
        const float4* __restrict__ hd = h4 + (long long)d * (N_HID / 4);

        // First half: 4 independent 16B loads in flight.
        float4 a0 = __ldg(hs + sub);
        float4 a1 = __ldg(hs + sub + 8);
        float4 b0 = __ldg(hd + sub);
        float4 b1 = __ldg(hd + sub + 8);

        float acc;
        acc = a0.x * w0.x * b0.x;
        acc = fmaf(a0.y * w0.y, b0.y, acc);
        acc = fmaf(a0.z * w0.z, b0.z, acc);
        acc = fmaf(a0.w * w0.w, b0.w, acc);
        acc = fmaf(a1.x * w1.x, b1.x, acc);
        acc = fmaf(a1.y * w1.y, b1.y, acc);
        acc = fmaf(a1.z * w1.z, b1.z, acc);
        acc = fmaf(a1.w * w1.w, b1.w, acc);

        // Second half (registers of first half are dead by now).
        float4 a2 = __ldg(hs + sub + 16);
        float4 a3 = __ldg(hs + sub + 24);
        float4 b2 = __ldg(hd + sub + 16);
        float4 b3 = __ldg(hd + sub + 24);

        acc = fmaf(a2.x * w2.x, b2.x, acc);
        acc = fmaf(a2.y * w2.y, b2.y, acc);
        acc = fmaf(a2.z * w2.z, b2.z, acc);
        acc = fmaf(a2.w * w2.w, b2.w, acc);
        acc = fmaf(a3.x * w3.x, b3.x, acc);
        acc = fmaf(a3.y * w3.y, b3.y, acc);
        acc = fmaf(a3.z * w3.z, b3.z, acc);
        acc = fmaf(a3.w * w3.w, b3.w, acc);

        // Reduce across the 8-lane group.
        acc += __shfl_xor_sync(0xFFFFFFFFu, acc, 4);
        acc += __shfl_xor_sync(0xFFFFFFFFu, acc, 2);
        acc += __shfl_xor_sync(0xFFFFFFFFu, acc, 1);

        if (sub == 0)
            outR[e] = 1.0f / (1.0f + __expf(-acc));
    }
}

extern "C" void kernel_launch(void* const* d_in, const int* in_sizes, int n_in,
                              void* d_out, int out_size) {
    const float4* h4 = (const float4*)d_in[0];
    const float4* W4 = (const float4*)d_in[1];
    const int*   src = (const int*)d_in[2];
    const int*   dst = (const int*)d_in[3];
    float* out = (float*)d_out;

    dim3 grid(GRID_X, N_REL);
    distmult_kernel<<<grid, BLOCK>>>(h4, W4, src, dst, out);
}

// round 5
// speedup vs baseline: 1.9270x; 1.0104x over previous
#include <cuda_runtime.h>
#include <cuda_bf16.h>

// DistMult edge scoring:
//   out[r, e] = sigmoid( sum_d h[src[r,e], d] * W[r, d] * h[dst[r,e], d] )
// h [100000,128] f32, W [6,128] f32, src/dst [6,200000] int32, out [6,200000] f32.
//
// R5: same structure as R4 (8 lanes/edge, 4 edges/warp, W hoisted into
// registers, per-relation grid, 5 loop iters exactly) but the 8 row loads
// are issued as ONE front-batched burst (MLP 4 -> 8 per thread) to cover
// ~250-cycle L2 latency. R4 ncu: L2=60.7% leading pipe, occ capped at
// 4 CTAs by 64 regs -> latency-limited. Goal: push L2 toward saturation.

#define N_HID 128
#define E_PER_REL 200000
#define N_REL 6
#define BLOCK 256
#define EDGES_PER_BLOCK 32   // 256 threads / 8 lanes per edge
#define GRID_X 1250          // 1250 * 32 * 5 == 200000, no tail

__global__ __launch_bounds__(BLOCK, 4)
void distmult_kernel(const float4* __restrict__ h4,
                     const float4* __restrict__ W4,
                     const int* __restrict__ src_idx,
                     const int* __restrict__ dst_idx,
                     float* __restrict__ out) {
    const int rel   = blockIdx.y;
    const int sub   = threadIdx.x & 7;    // lane within 8-lane edge group
    const int group = threadIdx.x >> 3;   // edge slot within block: 0..31

    // This relation's W row in registers: lane sub owns chunks {sub, sub+8, sub+16, sub+24}.
    const float4* __restrict__ wr = W4 + rel * (N_HID / 4);
    const float4 w0 = __ldg(wr + sub);
    const float4 w1 = __ldg(wr + sub + 8);
    const float4 w2 = __ldg(wr + sub + 16);
    const float4 w3 = __ldg(wr + sub + 24);

    const int* __restrict__ srcR = src_idx + rel * E_PER_REL;
    const int* __restrict__ dstR = dst_idx + rel * E_PER_REL;
    float* __restrict__ outR = out + rel * E_PER_REL;

    for (int e = blockIdx.x * EDGES_PER_BLOCK + group; e < E_PER_REL;
         e += GRID_X * EDGES_PER_BLOCK) {
        const int s = __ldg(srcR + e);   // broadcast within the 8-lane group
        const int d = __ldg(dstR + e);

        const float4* __restrict__ hs = h4 + (long long)s * (N_HID / 4);
        const float4* __restrict__ hd = h4 + (long long)d * (N_HID / 4);

        // All 8 independent 16B loads in one burst: MLP=8 per thread,
        // 8 x 512B per warp in flight before any consumer.
        float4 a0 = __ldg(hs + sub);
        float4 a1 = __ldg(hs + sub + 8);
        float4 a2 = __ldg(hs + sub + 16);
        float4 a3 = __ldg(hs + sub + 24);
        float4 b0 = __ldg(hd + sub);
        float4 b1 = __ldg(hd + sub + 8);
        float4 b2 = __ldg(hd + sub + 16);
        float4 b3 = __ldg(hd + sub + 24);

        float acc;
        acc = a0.x * w0.x * b0.x;
        acc = fmaf(a0.y * w0.y, b0.y, acc);
        acc = fmaf(a0.z * w0.z, b0.z, acc);
        acc = fmaf(a0.w * w0.w, b0.w, acc);
        acc = fmaf(a1.x * w1.x, b1.x, acc);
        acc = fmaf(a1.y * w1.y, b1.y, acc);
        acc = fmaf(a1.z * w1.z, b1.z, acc);
        acc = fmaf(a1.w * w1.w, b1.w, acc);
        acc = fmaf(a2.x * w2.x, b2.x, acc);
        acc = fmaf(a2.y * w2.y, b2.y, acc);
        acc = fmaf(a2.z * w2.z, b2.z, acc);
        acc = fmaf(a2.w * w2.w, b2.w, acc);
        acc = fmaf(a3.x * w3.x, b3.x, acc);
        acc = fmaf(a3.y * w3.y, b3.y, acc);
        acc = fmaf(a3.z * w3.z, b3.z, acc);
        acc = fmaf(a3.w * w3.w, b3.w, acc);

        // Reduce across the 8-lane group.
        acc += __shfl_xor_sync(0xFFFFFFFFu, acc, 4);
        acc += __shfl_xor_sync(0xFFFFFFFFu, acc, 2);
        acc += __shfl_xor_sync(0xFFFFFFFFu, acc, 1);

        if (sub == 0)
            outR[e] = 1.0f / (1.0f + __expf(-acc));
    }
}

extern "C" void kernel_launch(void* const* d_in, const int* in_sizes, int n_in,
                              void* d_out, int out_size) {
    const float4* h4 = (const float4*)d_in[0];
    const float4* W4 = (const float4*)d_in[1];
    const int*   src = (const int*)d_in[2];
    const int*   dst = (const int*)d_in[3];
    float* out = (float*)d_out;

    dim3 grid(GRID_X, N_REL);
    distmult_kernel<<<grid, BLOCK>>>(h4, W4, src, dst, out);
}

// round 6
// speedup vs baseline: 2.1235x; 1.1020x over previous
#include <cuda_runtime.h>
#include <cuda_bf16.h>

// DistMult edge scoring:
//   out[r, e] = sigmoid( sum_d h[src[r,e], d] * W[r, d] * h[dst[r,e], d] )
// h [100000,128] f32, W [6,128] f32, src/dst [6,200000] int32, out [6,200000] f32.
//
// R6: break the per-iteration dependent chain (idx LDG -> row LDGs, two
// serialized ~250-cyc L2 round-trips). Each 8-lane group processes exactly
// 5 edges at compile-time stride 40000; preload all 5 (s,d) index pairs in
// the prologue, then unroll the 5 row phases so ptxas pipelines phase i+1's
// row loads under phase i's FMAs. R5 ncu: L2=61% leading, latency-exposed;
// traffic floor ~51us.

#define N_HID 128
#define E_PER_REL 200000
#define N_REL 6
#define BLOCK 256
#define EDGES_PER_BLOCK 32      // 256 threads / 8 lanes per edge
#define GRID_X 1250             // 1250 * 32 * 5 == 200000 exactly
#define ITERS 5
#define STRIDE (GRID_X * EDGES_PER_BLOCK)   // 40000

__global__ __launch_bounds__(BLOCK, 4)
void distmult_kernel(const float4* __restrict__ h4,
                     const float4* __restrict__ W4,
                     const int* __restrict__ src_idx,
                     const int* __restrict__ dst_idx,
                     float* __restrict__ out) {
    const int rel   = blockIdx.y;
    const int sub   = threadIdx.x & 7;    // lane within 8-lane edge group
    const int group = threadIdx.x >> 3;   // edge slot within block: 0..31

    // This relation's W row in registers: lane sub owns chunks {sub, sub+8, sub+16, sub+24}.
    const float4* __restrict__ wr = W4 + rel * (N_HID / 4);
    const float4 w0 = __ldg(wr + sub);
    const float4 w1 = __ldg(wr + sub + 8);
    const float4 w2 = __ldg(wr + sub + 16);
    const float4 w3 = __ldg(wr + sub + 24);

    const int* __restrict__ srcR = src_idx + rel * E_PER_REL;
    const int* __restrict__ dstR = dst_idx + rel * E_PER_REL;
    float* __restrict__ outR = out + rel * E_PER_REL;

    const int e0 = blockIdx.x * EDGES_PER_BLOCK + group;

    // Prologue: all 10 index loads in one independent burst (warp-uniform
    // within each 8-lane group). Removes the idx->row L2 serialization from
    // every phase.
    int s[ITERS], d[ITERS];
    #pragma unroll
    for (int i = 0; i < ITERS; i++) {
        s[i] = __ldg(srcR + e0 + i * STRIDE);
        d[i] = __ldg(dstR + e0 + i * STRIDE);
    }

    #pragma unroll
    for (int i = 0; i < ITERS; i++) {
        const float4* __restrict__ hs = h4 + (long long)s[i] * (N_HID / 4);
        const float4* __restrict__ hd = h4 + (long long)d[i] * (N_HID / 4);

        float4 a0 = __ldg(hs + sub);
        float4 a1 = __ldg(hs + sub + 8);
        float4 a2 = __ldg(hs + sub + 16);
        float4 a3 = __ldg(hs + sub + 24);
        float4 b0 = __ldg(hd + sub);
        float4 b1 = __ldg(hd + sub + 8);
        float4 b2 = __ldg(hd + sub + 16);
        float4 b3 = __ldg(hd + sub + 24);

        float acc;
        acc = a0.x * w0.x * b0.x;
        acc = fmaf(a0.y * w0.y, b0.y, acc);
        acc = fmaf(a0.z * w0.z, b0.z, acc);
        acc = fmaf(a0.w * w0.w, b0.w, acc);
        acc = fmaf(a1.x * w1.x, b1.x, acc);
        acc = fmaf(a1.y * w1.y, b1.y, acc);
        acc = fmaf(a1.z * w1.z, b1.z, acc);
        acc = fmaf(a1.w * w1.w, b1.w, acc);
        acc = fmaf(a2.x * w2.x, b2.x, acc);
        acc = fmaf(a2.y * w2.y, b2.y, acc);
        acc = fmaf(a2.z * w2.z, b2.z, acc);
        acc = fmaf(a2.w * w2.w, b2.w, acc);
        acc = fmaf(a3.x * w3.x, b3.x, acc);
        acc = fmaf(a3.y * w3.y, b3.y, acc);
        acc = fmaf(a3.z * w3.z, b3.z, acc);
        acc = fmaf(a3.w * w3.w, b3.w, acc);

        // Reduce across the 8-lane group.
        acc += __shfl_xor_sync(0xFFFFFFFFu, acc, 4);
        acc += __shfl_xor_sync(0xFFFFFFFFu, acc, 2);
        acc += __shfl_xor_sync(0xFFFFFFFFu, acc, 1);

        if (sub == 0)
            outR[e0 + i * STRIDE] = 1.0f / (1.0f + __expf(-acc));
    }
}

extern "C" void kernel_launch(void* const* d_in, const int* in_sizes, int n_in,
                              void* d_out, int out_size) {
    const float4* h4 = (const float4*)d_in[0];
    const float4* W4 = (const float4*)d_in[1];
    const int*   src = (const int*)d_in[2];
    const int*   dst = (const int*)d_in[3];
    float* out = (float*)d_out;

    dim3 grid(GRID_X, N_REL);
    distmult_kernel<<<grid, BLOCK>>>(h4, W4, src, dst, out);
}